// round 5
// baseline (speedup 1.0000x reference)
#include <cuda_runtime.h>
#include <cstddef>

// LoG = GaussianBlur(3,sigma=1) -> Laplacian(ksize=9) + 1, clip [0,255].
// Fused: composite 11x11 = A(x)B(y) + B(x)A(y), A = g3*S9, B = g3*D2_9.
// Reflect-101 pad of 5 on input == staged reflect pads (symmetric kernels).

#define Hn 512
#define Wn 512
#define ROWF 1536            // floats per image row (512*3)
#define TH 32
#define TWP 32
#define HALO 5
#define IN_H 42
#define IN_PITCH 132         // interleaved floats per smem row = 33 float4
#define IN_F4 33
#define HPP 68               // (A,B)-interleaved row pitch
#define HAB_PLANE 2860       // 42*68 + 4 pad
#define NTHREADS 512

__device__ __forceinline__ int reflect101(int i, int n) {
    i = (i < 0) ? -i : i;
    return (i >= n) ? (2 * n - 2 - i) : i;
}

__device__ __forceinline__ unsigned long long pk2(float lo, float hi) {
    unsigned long long r;
    asm("mov.b64 %0, {%1, %2};" : "=l"(r) : "f"(lo), "f"(hi));
    return r;
}
#define FMA2(acc, k, v) \
    asm("fma.rn.f32x2 %0, %1, %2, %0;" : "+l"(acc) : "l"(k), "l"(v))

__global__ __launch_bounds__(NTHREADS, 3)
void log_fused_kernel(const float* __restrict__ x, float* __restrict__ out) {
    extern __shared__ float smem[];
    float* in_s  = smem;                           // [42][132] interleaved input floats
    float* hAB_s = smem + IN_H * IN_PITCH;         // 3 planes [42][HPP], (A,B) pairs

    const float cA[11] = {
        0.274068619061f,  2.644411714f, 11.562892048f, 30.192548953f,
        52.163039333f,   62.326078667f, 52.163039333f, 30.192548953f,
        11.562892048f,    2.644411714f,  0.274068619061f };
    const float cB[11] = {
        0.274068619061f,  1.548137238f,  3.177794143f,  1.807451048f,
       -3.451862762f,    -6.711176571f, -3.451862762f,  1.807451048f,
        3.177794143f,     1.548137238f,  0.274068619061f };

    const int tid = threadIdx.x;
    const int h0  = blockIdx.y * TH;
    const int p0  = blockIdx.x * TWP;
    const size_t plane = (size_t)blockIdx.z * (size_t)(Hn * ROWF);
    const float* xp = x + plane;

    // ====== Phase 1: gmem -> smem straight interleaved copy (reflect rows) ===
    // smem row r, col j holds input float F = 3*p0 - 16 + j (16B aligned base).
    if (p0 != 0 && p0 != (Wn - TWP)) {
        const float4* gbase = (const float4*)(xp + 3 * p0 - 16);
        float4* s4 = (float4*)in_s;
        #pragma unroll
        for (int k = 0; k < 3; k++) {
            const int idx = tid + k * NTHREADS;
            if (idx < IN_H * IN_F4) {
                const int r  = idx / IN_F4;
                const int c4 = idx - r * IN_F4;
                const int gh = reflect101(h0 - HALO + r, Hn);
                s4[idx] = gbase[gh * (ROWF / 4) + c4];
            }
        }
    } else {
        // border in W: scalar with per-float pixel reflection
        for (int v = tid; v < 4 * IN_PITCH; v += NTHREADS) {
            const int col = v % IN_PITCH;
            const int rg  = v / IN_PITCH;              // 0..3
            const int F   = 3 * p0 - 16 + col;
            const int P   = (F + 48) / 3 - 16;         // floor(F/3)
            const int ch  = F - 3 * P;
            const int sp  = reflect101(P, Wn);
            const int srcf = 3 * sp + ch;
            for (int r = rg; r < IN_H; r += 4) {
                const int gh = reflect101(h0 - HALO + r, Hn);
                in_s[r * IN_PITCH + col] = xp[(size_t)gh * ROWF + srcf];
            }
        }
    }
    __syncthreads();

    // ====== Phase 2: horizontal 11-tap, interleaved reads, all channels ======
    // Task = (4-pixel segment s, row r): reads 11 float4 (44 floats, uses 1..42),
    // computes A,B for 4 pixels x 3 channels. All channel demux compile-time.
    if (tid < 336) {
        const int s = tid / IN_H;                     // 0..7
        const int r = tid - s * IN_H;
        const float4* src4 = (const float4*)(in_s + r * IN_PITCH) + 3 * s;

        float aA[3][4], aB[3][4];
        #pragma unroll
        for (int ch = 0; ch < 3; ch++)
            #pragma unroll
            for (int j = 0; j < 4; j++) { aA[ch][j] = 0.f; aB[ch][j] = 0.f; }

        #pragma unroll
        for (int k = 0; k < 11; k++) {
            float4 w = src4[k];
            float ws[4] = {w.x, w.y, w.z, w.w};
            #pragma unroll
            for (int u = 0; u < 4; u++) {
                const int i = 4 * k + u;              // local float index
                if (i >= 1 && i <= 42) {
                    const int m  = (i - 1) / 3;       // local pixel 0..13
                    const int ch = (i - 1) % 3;
                    const float v = ws[u];
                    #pragma unroll
                    for (int j = 0; j < 4; j++) {
                        const int t = m - j;
                        if (t >= 0 && t < 11) {
                            aA[ch][j] = fmaf(cA[t], v, aA[ch][j]);
                            aB[ch][j] = fmaf(cB[t], v, aB[ch][j]);
                        }
                    }
                }
            }
        }
        #pragma unroll
        for (int ch = 0; ch < 3; ch++) {
            float4* d = (float4*)(hAB_s + ch * HAB_PLANE + r * HPP + 8 * s);
            d[0] = make_float4(aA[ch][0], aB[ch][0], aA[ch][1], aB[ch][1]);
            d[1] = make_float4(aA[ch][2], aB[ch][2], aA[ch][3], aB[ch][3]);
        }
    }
    __syncthreads();

    // ====== Phase 3: vertical 11-tap combine, pixel-pair, packed f32x2 FMA ===
    // 48 (pair,ch) columns x 8 chunks of 4 rows = 384 tasks.
    if (tid < 384) {
        const int q     = tid % 48;
        const int chunk = tid / 48;
        const int c  = q % 3;
        const int pp = q / 3;
        const int r0 = chunk * 4;
        const float4* s = (const float4*)(hAB_s + c * HAB_PLANE + r0 * HPP) + pp;

        unsigned long long acc[4];
        #pragma unroll
        for (int j = 0; j < 4; j++) acc[j] = pk2(1.0f, 1.0f);   // delta = 1

        #pragma unroll
        for (int i = 0; i < 14; i++) {
            float4 v = s[i * (HPP / 4)];                         // (A0,B0,A1,B1)
            unsigned long long a01 = pk2(v.x, v.z);
            unsigned long long b01 = pk2(v.y, v.w);
            #pragma unroll
            for (int j = 0; j < 4; j++) {
                const int t = i - j;
                if (t >= 0 && t < 11) {
                    unsigned long long kb = pk2(cB[t], cB[t]);   // CSE: 6 distinct
                    unsigned long long ka = pk2(cA[t], cA[t]);
                    FMA2(acc[j], kb, a01);
                    FMA2(acc[j], ka, b01);
                }
            }
        }
        float* op = out + plane + (size_t)(h0 + r0) * ROWF + (p0 + 2 * pp) * 3 + c;
        #pragma unroll
        for (int j = 0; j < 4; j++) {
            float o0, o1;
            asm("mov.b64 {%0, %1}, %2;" : "=f"(o0), "=f"(o1) : "l"(acc[j]));
            op[j * ROWF]     = fminf(fmaxf(o0, 0.0f), 255.0f);
            op[j * ROWF + 3] = fminf(fmaxf(o1, 0.0f), 255.0f);
        }
    }
}

extern "C" void kernel_launch(void* const* d_in, const int* in_sizes, int n_in,
                              void* d_out, int out_size) {
    const float* x = (const float*)d_in[0];
    float* out = (float*)d_out;
    const int N = in_sizes[0] / (Hn * Wn * 3);

    const int smem_bytes = (IN_H * IN_PITCH + 3 * HAB_PLANE) * (int)sizeof(float);
    cudaFuncSetAttribute(log_fused_kernel,
                         cudaFuncAttributeMaxDynamicSharedMemorySize, smem_bytes);

    dim3 grid(Wn / TWP, Hn / TH, N);   // (16, 16, N)
    log_fused_kernel<<<grid, NTHREADS, smem_bytes>>>(x, out);
}